// round 1
// baseline (speedup 1.0000x reference)
#include <cuda_runtime.h>
#include <math.h>

#define NN 50000
#define EE 1600000
#define HH 64
#define FIN 8
#define PP 5
#define LL 3
#define CI 68   // H + 4

// ---------------- scratch (device globals; no allocation) ----------------
__device__ float g_deg[NN];
__device__ float g_dis[NN];
__device__ int   g_cnt[NN];
__device__ int   g_fill[NN];
__device__ int   g_rowptr[NN + 1];
__device__ int   g_cols[EE];
__device__ float g_wv[EE];
__device__ float g_h[NN * HH];
__device__ float g_txA[NN * HH];   // reused as A (edge-pred) at the end
__device__ float g_txB[NN * HH];   // reused as B (edge-pred) at the end
__device__ float g_res[NN * HH];
__device__ float g_colsum[HH];
__device__ float g_sumsq;
__device__ float g_coeffs[PP + 1];

// ---------------- graph build ----------------
__global__ void zero_build_kernel() {
    int i = blockIdx.x * blockDim.x + threadIdx.x;
    if (i < NN) { g_deg[i] = 0.f; g_cnt[i] = 0; g_fill[i] = 0; }
}

__global__ void deghist_kernel(const int* __restrict__ ei, const float* __restrict__ ew) {
    int e = blockIdx.x * blockDim.x + threadIdx.x;
    if (e >= EE) return;
    atomicAdd(&g_deg[ei[EE + e]], ew[e]);   // deg at col
    atomicAdd(&g_cnt[ei[e]], 1);            // count at row
}

__global__ void dis_kernel() {
    int n = blockIdx.x * blockDim.x + threadIdx.x;
    if (n >= NN) return;
    float d = g_deg[n];
    float v = rsqrtf(d);           // d==0 -> inf
    v = fminf(v, 1e6f);            // clamp like reference
    g_dis[n] = v;
}

// single-block exclusive scan over g_cnt -> g_rowptr (N=50000, 1024 threads)
__global__ void scan_kernel() {
    __shared__ int part[1024];
    const int CHUNK = (NN + 1023) / 1024;   // 49
    int tid = threadIdx.x;
    int base = tid * CHUNK;
    int s = 0;
    for (int i = 0; i < CHUNK; ++i) {
        int idx = base + i;
        if (idx < NN) s += g_cnt[idx];
    }
    part[tid] = s;
    __syncthreads();
    for (int off = 1; off < 1024; off <<= 1) {
        int v = (tid >= off) ? part[tid - off] : 0;
        __syncthreads();
        part[tid] += v;
        __syncthreads();
    }
    int run = (tid == 0) ? 0 : part[tid - 1];
    for (int i = 0; i < CHUNK; ++i) {
        int idx = base + i;
        if (idx < NN) { g_rowptr[idx] = run; run += g_cnt[idx]; }
    }
    if (tid == 1023) g_rowptr[NN] = run;   // == EE
}

__global__ void scatter_kernel(const int* __restrict__ ei, const float* __restrict__ ew) {
    int e = blockIdx.x * blockDim.x + threadIdx.x;
    if (e >= EE) return;
    int r = ei[e], c = ei[EE + e];
    int pos = g_rowptr[r] + atomicAdd(&g_fill[r], 1);
    g_cols[pos] = c;
    g_wv[pos]   = g_dis[r] * ew[e] * g_dis[c];
}

// ---------------- input projection ----------------
__global__ void inproj_kernel(const float* __restrict__ x,
                              const float* __restrict__ W,
                              const float* __restrict__ b) {
    int g = blockIdx.x * blockDim.x + threadIdx.x;
    if (g >= NN * HH) return;
    int n = g >> 6, f = g & 63;
    float s = b[f];
#pragma unroll
    for (int i = 0; i < FIN; ++i) s += x[n * FIN + i] * W[f * FIN + i];
    g_h[g] = s;
}

// ---------------- per-layer stats + coeff MLP ----------------
__global__ void zero_stats_kernel() {
    int t = threadIdx.x;
    if (t < HH) g_colsum[t] = 0.f;
    if (t == HH) g_sumsq = 0.f;
}

__global__ void stats_kernel() {
    __shared__ float red[256];
    int tid = threadIdx.x;
    int colf = tid & 63;
    float ls = 0.f, lss = 0.f;
    for (int n = blockIdx.x * 4 + (tid >> 6); n < NN; n += gridDim.x * 4) {
        float v = g_h[n * HH + colf];
        ls += v; lss += v * v;
    }
    red[tid] = ls;
    __syncthreads();
    if (tid < 64) {
        float c = red[tid] + red[tid + 64] + red[tid + 128] + red[tid + 192];
        atomicAdd(&g_colsum[tid], c);
    }
    __syncthreads();
    red[tid] = lss;
    __syncthreads();
    for (int o = 128; o > 0; o >>= 1) {
        if (tid < o) red[tid] += red[tid + o];
        __syncthreads();
    }
    if (tid == 0) atomicAdd(&g_sumsq, red[0]);
}

__global__ void coeff_kernel(const float* __restrict__ cW1, const float* __restrict__ cb1,
                             const float* __restrict__ cW2, const float* __restrict__ cb2) {
    __shared__ float ci[CI];
    __shared__ float hid[32];
    __shared__ float logit[PP + 1];
    int t = threadIdx.x;
    if (t < HH) ci[t] = g_colsum[t] / (float)NN;
    __syncthreads();
    if (t == 0) {
        float tot = 0.f;
        for (int i = 0; i < HH; ++i) tot += g_colsum[i];
        const float M = (float)NN * (float)HH;
        float mean = tot / M;
        float var  = (g_sumsq - tot * tot / M) / (M - 1.0f);   // unbiased
        ci[64] = mean;
        ci[65] = sqrtf(fmaxf(var, 0.f));
        ci[66] = (float)NN;
        ci[67] = (float)EE;
    }
    __syncthreads();
    if (t < 32) {
        float s = cb1[t];
        for (int i = 0; i < CI; ++i) s += cW1[t * CI + i] * ci[i];
        hid[t] = fmaxf(s, 0.f);
    }
    __syncthreads();
    if (t < PP + 1) {
        float s = cb2[t];
        for (int i = 0; i < 32; ++i) s += cW2[t * 32 + i] * hid[i];
        logit[t] = s;
    }
    __syncthreads();
    if (t == 0) {
        float mx = logit[0];
        for (int i = 1; i <= PP; ++i) mx = fmaxf(mx, logit[i]);
        float den = 0.f, ex[PP + 1];
        for (int i = 0; i <= PP; ++i) { ex[i] = expf(logit[i] - mx); den += ex[i]; }
        for (int i = 0; i <= PP; ++i) g_coeffs[i] = ex[i] / den;
    }
}

// ---------------- SpMM (gather-CSR, warp per row, no atomics) ----------------
__global__ void spmm_kernel(int k) {
    int gw = (blockIdx.x * blockDim.x + threadIdx.x) >> 5;
    if (gw >= NN) return;
    int lane = threadIdx.x & 31;

    const float* tin; float* tout;
    if (k == 1)      { tin = g_h;   tout = g_txA; }
    else if (k & 1)  { tin = g_txB; tout = g_txA; }
    else             { tin = g_txA; tout = g_txB; }

    int s = g_rowptr[gw], e = g_rowptr[gw + 1];
    float ax = 0.f, ay = 0.f;
    const float2* tv = (const float2*)tin;
#pragma unroll 4
    for (int j = s; j < e; ++j) {
        int cc  = __ldg(&g_cols[j]);      // broadcast (all lanes same addr, L1 hit)
        float w = __ldg(&g_wv[j]);
        float2 v = __ldg(&tv[cc * 32 + lane]);   // 256B coalesced per warp
        ax += w * v.x; ay += w * v.y;
    }
    int o = gw * 32 + lane;
    ((float2*)tout)[o] = make_float2(ax, ay);

    float ck = g_coeffs[k];
    float2 r;
    if (k == 1) {
        float2 hv = ((const float2*)g_h)[o];
        float c0 = g_coeffs[0];
        r.x = c0 * hv.x + ck * ax;
        r.y = c0 * hv.y + ck * ay;
    } else {
        r = ((float2*)g_res)[o];
        r.x += ck * ax;
        r.y += ck * ay;
    }
    ((float2*)g_res)[o] = r;
}

// ---------------- residual + LayerNorm (warp per node) ----------------
__global__ void ln_kernel(const float* __restrict__ scale, const float* __restrict__ bias,
                          float* outh) {
    int gw = (blockIdx.x * blockDim.x + threadIdx.x) >> 5;
    if (gw >= NN) return;
    int lane = threadIdx.x & 31;
    int o = gw * 32 + lane;
    float2 hv = ((const float2*)g_h)[o];
    float2 rv = ((const float2*)g_res)[o];
    float vx = hv.x + rv.x, vy = hv.y + rv.y;
    float s = vx + vy;
#pragma unroll
    for (int d = 16; d; d >>= 1) s += __shfl_xor_sync(0xffffffffu, s, d);
    float m = s * (1.0f / HH);
    float dx = vx - m, dy = vy - m;
    float q = dx * dx + dy * dy;
#pragma unroll
    for (int d = 16; d; d >>= 1) q += __shfl_xor_sync(0xffffffffu, q, d);
    float inv = rsqrtf(q * (1.0f / HH) + 1e-5f);
    float ox = dx * inv * scale[2 * lane]     + bias[2 * lane];
    float oy = dy * inv * scale[2 * lane + 1] + bias[2 * lane + 1];
    ((float2*)g_h)[o] = make_float2(ox, oy);
    if (outh) ((float2*)outh)[o] = make_float2(ox, oy);
}

// ---------------- edge predictor: A = h@W1a^T, B = h@W1b^T ----------------
__global__ void abgemm_kernel(const float* __restrict__ epW1) {
    __shared__ float WtA[64 * 64];
    __shared__ float WtB[64 * 64];
    __shared__ float hs[4 * 64];
    int tid = threadIdx.x;
    for (int idx = tid; idx < 4096; idx += 256) {
        int f = idx >> 6, i = idx & 63;
        WtA[i * 64 + f] = epW1[f * 128 + i];        // W1[:, :64]
        WtB[i * 64 + f] = epW1[f * 128 + 64 + i];   // W1[:, 64:]
    }
    int n0 = blockIdx.x * 4;
    hs[tid] = g_h[n0 * 64 + tid];
    __syncthreads();
    int ln = tid >> 6, f = tid & 63;
    float a = 0.f, b = 0.f;
#pragma unroll
    for (int i = 0; i < 64; ++i) {
        float hv = hs[ln * 64 + i];
        a += hv * WtA[i * 64 + f];
        b += hv * WtB[i * 64 + f];
    }
    g_txA[(n0 + ln) * 64 + f] = a;
    g_txB[(n0 + ln) * 64 + f] = b;
}

__global__ void __launch_bounds__(128)
edge_kernel(const int* __restrict__ ei,
            const float* __restrict__ epb1,
            const float* __restrict__ epW2, const float* __restrict__ epb2,
            const float* __restrict__ epW3, const float* __restrict__ epb3,
            float* __restrict__ out) {
    __shared__ float W2s[32 * 64];
    __shared__ float b1s[64];
    __shared__ float b2s[32];
    __shared__ float W3s[32];
    __shared__ float b3s;
    int tid = threadIdx.x;
    for (int idx = tid; idx < 2048; idx += 128) W2s[idx] = epW2[idx];
    if (tid < 64) b1s[tid] = epb1[tid];
    if (tid < 32) { b2s[tid] = epb2[tid]; W3s[tid] = epW3[tid]; }
    if (tid == 0) b3s = epb3[0];
    __syncthreads();

    int e = blockIdx.x * 128 + tid;
    if (e >= EE) return;
    int r = ei[e], c = ei[EE + e];
    const float4* Ar = (const float4*)(g_txA + r * 64);
    const float4* Bc = (const float4*)(g_txB + c * 64);
    const float4* b1v = (const float4*)b1s;
    float e1[64];
#pragma unroll
    for (int i = 0; i < 16; ++i) {
        float4 av = __ldg(&Ar[i]);
        float4 bv = __ldg(&Bc[i]);
        float4 bb = b1v[i];
        e1[4 * i + 0] = fmaxf(av.x + bv.x + bb.x, 0.f);
        e1[4 * i + 1] = fmaxf(av.y + bv.y + bb.y, 0.f);
        e1[4 * i + 2] = fmaxf(av.z + bv.z + bb.z, 0.f);
        e1[4 * i + 3] = fmaxf(av.w + bv.w + bb.w, 0.f);
    }
    float acc = b3s;
#pragma unroll
    for (int o = 0; o < 32; ++o) {
        float s = b2s[o];
        const float4* wv = (const float4*)(W2s + o * 64);
#pragma unroll
        for (int i = 0; i < 16; ++i) {
            float4 w = wv[i];
            s += w.x * e1[4 * i] + w.y * e1[4 * i + 1] + w.z * e1[4 * i + 2] + w.w * e1[4 * i + 3];
        }
        acc += W3s[o] * fmaxf(s, 0.f);
    }
    out[e] = 1.0f / (1.0f + expf(-acc));
}

// ---------------- launch ----------------
extern "C" void kernel_launch(void* const* d_in, const int* in_sizes, int n_in,
                              void* d_out, int out_size) {
    const float* x    = (const float*)d_in[0];
    const int*   ei   = (const int*)d_in[1];
    const float* ew   = (const float*)d_in[2];
    const float* W_in = (const float*)d_in[3];
    const float* b_in = (const float*)d_in[4];
    const float* cW1  = (const float*)d_in[5];
    const float* cb1  = (const float*)d_in[6];
    const float* cW2  = (const float*)d_in[7];
    const float* cb2  = (const float*)d_in[8];
    const float* lns  = (const float*)d_in[9];
    const float* lnb  = (const float*)d_in[10];
    const float* epW1 = (const float*)d_in[11];
    const float* epb1 = (const float*)d_in[12];
    const float* epW2 = (const float*)d_in[13];
    const float* epb2 = (const float*)d_in[14];
    const float* epW3 = (const float*)d_in[15];
    const float* epb3 = (const float*)d_in[16];
    float* out = (float*)d_out;

    const int NB = (NN + 255) / 256;
    const int EB = (EE + 255) / 256;
    const int WB = (NN * 32 + 255) / 256;   // warp-per-node grids (6250)

    // graph build (CSR + symmetric normalization)
    zero_build_kernel<<<NB, 256>>>();
    deghist_kernel<<<EB, 256>>>(ei, ew);
    dis_kernel<<<NB, 256>>>();
    scan_kernel<<<1, 1024>>>();
    scatter_kernel<<<EB, 256>>>(ei, ew);

    // input projection
    inproj_kernel<<<(NN * HH + 255) / 256, 256>>>(x, W_in, b_in);

    // diffusion layers
    for (int l = 0; l < LL; ++l) {
        zero_stats_kernel<<<1, 128>>>();
        stats_kernel<<<1024, 256>>>();
        coeff_kernel<<<1, 128>>>(cW1 + l * 32 * CI, cb1 + l * 32,
                                 cW2 + l * (PP + 1) * 32, cb2 + l * (PP + 1));
        for (int k = 1; k <= PP; ++k)
            spmm_kernel<<<WB, 256>>>(k);
        ln_kernel<<<WB, 256>>>(lns + l * HH, lnb + l * HH,
                               (l == LL - 1) ? (out + EE) : (float*)nullptr);
    }

    // edge predictor
    abgemm_kernel<<<NN / 4, 256>>>(epW1);
    edge_kernel<<<(EE + 127) / 128, 128>>>(ei, epb1, epW2, epb2, epW3, epb3, out);
}